// round 2
// baseline (speedup 1.0000x reference)
#include <cuda_runtime.h>

#define NBLK  1184
#define NTHR  256
#define NBINS 64

// Scratch (no allocations allowed): per-block partials + params + accumulators.
__device__ float4 g_part[NBLK];     // per-block {min, max, sum, sumsq}
__device__ float  g_params[4];      // scale, bias, e_top(=edges[64])
__device__ int    g_counts[NBINS];
__device__ int    g_ntop;

__device__ __forceinline__ float warp_min(float v) {
    #pragma unroll
    for (int o = 16; o; o >>= 1) v = fminf(v, __shfl_xor_sync(0xffffffffu, v, o));
    return v;
}
__device__ __forceinline__ float warp_max(float v) {
    #pragma unroll
    for (int o = 16; o; o >>= 1) v = fmaxf(v, __shfl_xor_sync(0xffffffffu, v, o));
    return v;
}
__device__ __forceinline__ float warp_sum(float v) {
    #pragma unroll
    for (int o = 16; o; o >>= 1) v += __shfl_xor_sync(0xffffffffu, v, o);
    return v;
}
__device__ __forceinline__ int warp_sumi(int v) {
    #pragma unroll
    for (int o = 16; o; o >>= 1) v += __shfl_xor_sync(0xffffffffu, v, o);
    return v;
}

// ---------------- Pass 1: min / max / sum / sumsq ----------------
__global__ void __launch_bounds__(NTHR) reduce_kernel(const float* __restrict__ x, int n)
{
    const float4* __restrict__ x4 = (const float4*)x;
    int n4     = n >> 2;
    int stride = gridDim.x * blockDim.x;
    int tid    = blockIdx.x * blockDim.x + threadIdx.x;

    float inf = __int_as_float(0x7f800000);
    float mnA = inf, mnB = inf, mxA = -inf, mxB = -inf;
    float s0 = 0.f, s1 = 0.f, q0 = 0.f, q1 = 0.f;

    for (int i = tid; i < n4; i += stride) {
        float4 v = x4[i];
        mnA = fminf(mnA, fminf(v.x, v.y));
        mnB = fminf(mnB, fminf(v.z, v.w));
        mxA = fmaxf(mxA, fmaxf(v.x, v.y));
        mxB = fmaxf(mxB, fmaxf(v.z, v.w));
        s0 += v.x + v.y;
        s1 += v.z + v.w;
        q0 = fmaf(v.x, v.x, q0);
        q0 = fmaf(v.y, v.y, q0);
        q1 = fmaf(v.z, v.z, q1);
        q1 = fmaf(v.w, v.w, q1);
    }
    // tail (n may not be divisible by 4)
    for (int i = (n4 << 2) + tid; i < n; i += stride) {
        float v = x[i];
        mnA = fminf(mnA, v);
        mxA = fmaxf(mxA, v);
        s0 += v;
        q0 = fmaf(v, v, q0);
    }

    float lmn = warp_min(fminf(mnA, mnB));
    float lmx = warp_max(fmaxf(mxA, mxB));
    float ls  = warp_sum(s0 + s1);
    float lq  = warp_sum(q0 + q1);

    __shared__ float4 sred[NTHR / 32];
    int w = threadIdx.x >> 5, l = threadIdx.x & 31;
    if (l == 0) sred[w] = make_float4(lmn, lmx, ls, lq);
    __syncthreads();
    if (w == 0) {
        float4 v = (l < NTHR / 32) ? sred[l] : make_float4(inf, -inf, 0.f, 0.f);
        float a = warp_min(v.x);
        float b = warp_max(v.y);
        float c = warp_sum(v.z);
        float d = warp_sum(v.w);
        if (l == 0) g_part[blockIdx.x] = make_float4(a, b, c, d);
    }
}

// ---------------- Pass 2: final reduce + edges + scratch reset ----------------
__global__ void __launch_bounds__(256) setup_kernel(float* __restrict__ out, int n)
{
    int tid = threadIdx.x;
    if (tid < NBINS)  g_counts[tid] = 0;
    if (tid == NBINS) g_ntop = 0;

    float inf = __int_as_float(0x7f800000);
    float mnA = inf, mxA = -inf, s = 0.f, q = 0.f;
    for (int i = tid; i < NBLK; i += 256) {
        float4 v = g_part[i];
        mnA = fminf(mnA, v.x);
        mxA = fmaxf(mxA, v.y);
        s += v.z;
        q += v.w;
    }
    mnA = warp_min(mnA); mxA = warp_max(mxA); s = warp_sum(s); q = warp_sum(q);

    __shared__ float4 sred[8];
    __shared__ float  fin[4];
    int w = tid >> 5, l = tid & 31;
    if (l == 0) sred[w] = make_float4(mnA, mxA, s, q);
    __syncthreads();
    if (w == 0) {
        float4 v = (l < 8) ? sred[l] : make_float4(inf, -inf, 0.f, 0.f);
        float a = warp_min(v.x);
        float b = warp_max(v.y);
        float c = warp_sum(v.z);
        float d = warp_sum(v.w);
        if (l == 0) { fin[0] = a; fin[1] = b; fin[2] = c; fin[3] = d; }
    }
    __syncthreads();

    float mn = fin[0], mx = fin[1];
    float r  = __fadd_rn(mx, -mn);          // fl(mx - mn), matches reference
    if (tid == 0) {
        out[0] = mn;
        out[1] = mx;
        out[2] = (float)n;                  // 64e6 exactly representable
        out[3] = fin[2];
        out[4] = fin[3];
        float scale = __fdiv_rn(64.0f, r);
        g_params[0] = scale;
        g_params[1] = -mn * scale;          // bias for fused bin compute
        g_params[2] = __fadd_rn(mn, r);     // edges[64] (overflow boundary)
    }
    if (tid <= NBINS) {
        // edges[j] = fl(mn + fl(r * fl(j/64))) — j/64 is exact dyadic, unfused ops
        float frac = (float)tid * 0.015625f;
        float e    = __fadd_rn(mn, __fmul_rn(r, frac));
        out[5 + tid] = e;
    }
}

// ---------------- Pass 3: histogram ----------------
__global__ void __launch_bounds__(NTHR) hist_kernel(const float* __restrict__ x, int n)
{
    __shared__ int sh[NBINS];
    if (threadIdx.x < NBINS) sh[threadIdx.x] = 0;
    __syncthreads();

    float scale = g_params[0];
    float bias  = g_params[1];
    float etop  = g_params[2];

    const float4* __restrict__ x4 = (const float4*)x;
    int n4     = n >> 2;
    int stride = gridDim.x * blockDim.x;
    int tid    = blockIdx.x * blockDim.x + threadIdx.x;
    int ntop   = 0;

    for (int i = tid; i < n4; i += stride) {
        float4 v = x4[i];
        float t0 = fmaf(v.x, scale, bias);
        float t1 = fmaf(v.y, scale, bias);
        float t2 = fmaf(v.z, scale, bias);
        float t3 = fmaf(v.w, scale, bias);
        int b0 = min((int)t0, 63);   // t >= ~0 by construction; trunc(-eps)=0
        int b1 = min((int)t1, 63);
        int b2 = min((int)t2, 63);
        int b3 = min((int)t3, 63);
        ntop += (v.x >= etop) + (v.y >= etop) + (v.z >= etop) + (v.w >= etop);
        atomicAdd(&sh[b0], 1);
        atomicAdd(&sh[b1], 1);
        atomicAdd(&sh[b2], 1);
        atomicAdd(&sh[b3], 1);
    }
    for (int i = (n4 << 2) + tid; i < n; i += stride) {
        float v = x[i];
        int  b = min((int)fmaf(v, scale, bias), 63);
        ntop += (v >= etop);
        atomicAdd(&sh[b], 1);
    }

    ntop = warp_sumi(ntop);
    __shared__ int swn[NTHR / 32];
    int w = threadIdx.x >> 5, l = threadIdx.x & 31;
    if (l == 0) swn[w] = ntop;
    __syncthreads();   // also orders all shared-hist atomics before the flush
    if (threadIdx.x == 0) {
        int t = 0;
        #pragma unroll
        for (int i = 0; i < NTHR / 32; i++) t += swn[i];
        if (t) atomicAdd(&g_ntop, t);
    }
    if (threadIdx.x < NBINS) atomicAdd(&g_counts[threadIdx.x], sh[threadIdx.x]);
}

// ---------------- Pass 4: finalize counts ----------------
__global__ void __launch_bounds__(NBINS) finalize_kernel(float* __restrict__ out)
{
    int i = threadIdx.x;
    int c = g_counts[i];
    // Reference: elements >= edges[64] fall in no bin; then counts[-1] += 1.
    // We clamped them into bin 63, so subtract n_top and add the +1.
    if (i == NBINS - 1) c += 1 - g_ntop;
    out[5 + 65 + i] = (float)c;
}

extern "C" void kernel_launch(void* const* d_in, const int* in_sizes, int n_in,
                              void* d_out, int out_size)
{
    const float* x = (const float*)d_in[0];
    int n = in_sizes[0];
    float* out = (float*)d_out;

    reduce_kernel  <<<NBLK, NTHR>>>(x, n);
    setup_kernel   <<<1,    256 >>>(out, n);
    hist_kernel    <<<NBLK, NTHR>>>(x, n);
    finalize_kernel<<<1,   NBINS>>>(out);
}

// round 6
// speedup vs baseline: 1.0381x; 1.0381x over previous
#include <cuda_runtime.h>

#define NBLK  1216          // 152 SMs x 8 CTAs
#define NTHR  256
#define NBINS 64

// Scratch (no allocations allowed).
__device__ float4 g_part[NBLK];     // per-block {min, max, sum, sumsq}
__device__ float  g_params[3];      // scale, bias, e_top(=edges[64])
__device__ int    g_counts[NBINS];
__device__ int    g_ntop;
__device__ int    g_sem1;           // zero-init; self-resetting tickets
__device__ int    g_sem2;

__device__ __forceinline__ float warp_min(float v) {
    #pragma unroll
    for (int o = 16; o; o >>= 1) v = fminf(v, __shfl_xor_sync(0xffffffffu, v, o));
    return v;
}
__device__ __forceinline__ float warp_max(float v) {
    #pragma unroll
    for (int o = 16; o; o >>= 1) v = fmaxf(v, __shfl_xor_sync(0xffffffffu, v, o));
    return v;
}
__device__ __forceinline__ float warp_sum(float v) {
    #pragma unroll
    for (int o = 16; o; o >>= 1) v += __shfl_xor_sync(0xffffffffu, v, o);
    return v;
}
__device__ __forceinline__ int warp_sumi(int v) {
    #pragma unroll
    for (int o = 16; o; o >>= 1) v += __shfl_xor_sync(0xffffffffu, v, o);
    return v;
}

// accumulate one float4 into one accumulator set
#define ACC(v, mn, mx, s, q)                                        \
    do {                                                            \
        mn = fminf(mn, fminf(fminf(v.x, v.y), fminf(v.z, v.w)));    \
        mx = fmaxf(mx, fmaxf(fmaxf(v.x, v.y), fmaxf(v.z, v.w)));    \
        s += (v.x + v.y) + (v.z + v.w);                             \
        q = fmaf(v.x, v.x, q); q = fmaf(v.y, v.y, q);               \
        q = fmaf(v.z, v.z, q); q = fmaf(v.w, v.w, q);               \
    } while (0)

// ---------------- Pass 1: min/max/sum/sumsq + fused finalization ----------------
__global__ void __launch_bounds__(NTHR) reduce_kernel(const float* __restrict__ x,
                                                      int n, float* __restrict__ out)
{
    const float4* __restrict__ x4 = (const float4*)x;
    int n4     = n >> 2;
    int stride = gridDim.x * blockDim.x;
    int tid    = blockIdx.x * blockDim.x + threadIdx.x;

    float inf = __int_as_float(0x7f800000);
    float mn0 = inf, mn1 = inf, mx0 = -inf, mx1 = -inf;
    float s0 = 0.f, s1 = 0.f, q0 = 0.f, q1 = 0.f;

    // MLP=4: four independent 128-bit loads in flight per iteration
    int i = tid;
    for (; i < n4 - 3 * stride; i += 4 * stride) {
        float4 a = x4[i];
        float4 b = x4[i + stride];
        float4 c = x4[i + 2 * stride];
        float4 d = x4[i + 3 * stride];
        ACC(a, mn0, mx0, s0, q0);
        ACC(b, mn1, mx1, s1, q1);
        ACC(c, mn0, mx0, s0, q0);
        ACC(d, mn1, mx1, s1, q1);
    }
    for (; i < n4; i += stride) {
        float4 a = x4[i];
        ACC(a, mn0, mx0, s0, q0);
    }
    for (int j = (n4 << 2) + tid; j < n; j += stride) {   // scalar tail
        float v = x[j];
        mn0 = fminf(mn0, v);
        mx0 = fmaxf(mx0, v);
        s0 += v;
        q0 = fmaf(v, v, q0);
    }

    float lmn = warp_min(fminf(mn0, mn1));
    float lmx = warp_max(fmaxf(mx0, mx1));
    float ls  = warp_sum(s0 + s1);
    float lq  = warp_sum(q0 + q1);

    __shared__ float4 sred[NTHR / 32];
    __shared__ int    lastflag;
    int w = threadIdx.x >> 5, l = threadIdx.x & 31;
    if (l == 0) sred[w] = make_float4(lmn, lmx, ls, lq);
    __syncthreads();
    if (w == 0) {
        float4 v = (l < NTHR / 32) ? sred[l] : make_float4(inf, -inf, 0.f, 0.f);
        float a = warp_min(v.x);
        float b = warp_max(v.y);
        float c = warp_sum(v.z);
        float d = warp_sum(v.w);
        if (l == 0) {
            g_part[blockIdx.x] = make_float4(a, b, c, d);
            __threadfence();
            lastflag = (atomicAdd(&g_sem1, 1) == (int)gridDim.x - 1);
        }
    }
    __syncthreads();
    if (!lastflag) return;

    // ---- last block: final reduce + edges + scratch reset ----
    __threadfence();
    int t = threadIdx.x;
    if (t < NBINS)      g_counts[t] = 0;
    if (t == NBINS)     g_ntop = 0;
    if (t == NBINS + 1) g_sem1 = 0;      // re-arm for next graph replay

    float mnA = inf, mxA = -inf, s = 0.f, q = 0.f;
    for (int k = t; k < NBLK; k += NTHR) {
        float4 v = g_part[k];
        mnA = fminf(mnA, v.x);
        mxA = fmaxf(mxA, v.y);
        s += v.z;
        q += v.w;
    }
    mnA = warp_min(mnA); mxA = warp_max(mxA); s = warp_sum(s); q = warp_sum(q);

    __shared__ float4 sred2[NTHR / 32];
    __shared__ float  fin[4];
    if (l == 0) sred2[w] = make_float4(mnA, mxA, s, q);
    __syncthreads();
    if (w == 0) {
        float4 v = (l < NTHR / 32) ? sred2[l] : make_float4(inf, -inf, 0.f, 0.f);
        float a = warp_min(v.x);
        float b = warp_max(v.y);
        float c = warp_sum(v.z);
        float d = warp_sum(v.w);
        if (l == 0) { fin[0] = a; fin[1] = b; fin[2] = c; fin[3] = d; }
    }
    __syncthreads();

    float mn = fin[0], mx = fin[1];
    float r  = __fadd_rn(mx, -mn);          // fl(mx - mn), matches reference
    if (t == 0) {
        out[0] = mn;
        out[1] = mx;
        out[2] = (float)n;
        out[3] = fin[2];
        out[4] = fin[3];
        float scale = __fdiv_rn(64.0f, r);
        g_params[0] = scale;
        g_params[1] = -mn * scale;
        g_params[2] = __fadd_rn(mn, r);     // edges[64] (overflow boundary)
    }
    if (t <= NBINS) {
        // edges[j] = fl(mn + fl(r * fl(j/64))) — j/64 exact dyadic, unfused ops
        float frac = (float)t * 0.015625f;
        out[5 + t] = __fadd_rn(mn, __fmul_rn(r, frac));
    }
}

// bin + count one float4 into warp-private histogram
#define BIN4(v, shw, ntop, scale, bias, etop)                      \
    do {                                                           \
        int b0 = min((int)fmaf(v.x, scale, bias), 63);             \
        int b1 = min((int)fmaf(v.y, scale, bias), 63);             \
        int b2 = min((int)fmaf(v.z, scale, bias), 63);             \
        int b3 = min((int)fmaf(v.w, scale, bias), 63);             \
        ntop += (v.x >= etop) + (v.y >= etop) +                    \
                (v.z >= etop) + (v.w >= etop);                     \
        atomicAdd(&shw[b0], 1);                                    \
        atomicAdd(&shw[b1], 1);                                    \
        atomicAdd(&shw[b2], 1);                                    \
        atomicAdd(&shw[b3], 1);                                    \
    } while (0)

// ---------------- Pass 2: histogram + fused finalization ----------------
__global__ void __launch_bounds__(NTHR) hist_kernel(const float* __restrict__ x,
                                                    int n, float* __restrict__ out)
{
    __shared__ int sh[NTHR / 32][NBINS];     // per-warp private histograms
    __shared__ int lastflag;
    int w = threadIdx.x >> 5, l = threadIdx.x & 31;
    ((int*)sh)[threadIdx.x]        = 0;
    ((int*)sh)[threadIdx.x + NTHR] = 0;
    __syncthreads();
    int* shw = sh[w];

    float scale = g_params[0];
    float bias  = g_params[1];
    float etop  = g_params[2];

    const float4* __restrict__ x4 = (const float4*)x;
    int n4     = n >> 2;
    int stride = gridDim.x * blockDim.x;
    int tid    = blockIdx.x * blockDim.x + threadIdx.x;
    int ntop   = 0;

    int i = tid;
    for (; i < n4 - 3 * stride; i += 4 * stride) {
        float4 a = x4[i];
        float4 b = x4[i + stride];
        float4 c = x4[i + 2 * stride];
        float4 d = x4[i + 3 * stride];
        BIN4(a, shw, ntop, scale, bias, etop);
        BIN4(b, shw, ntop, scale, bias, etop);
        BIN4(c, shw, ntop, scale, bias, etop);
        BIN4(d, shw, ntop, scale, bias, etop);
    }
    for (; i < n4; i += stride) {
        float4 a = x4[i];
        BIN4(a, shw, ntop, scale, bias, etop);
    }
    for (int j = (n4 << 2) + tid; j < n; j += stride) {
        float v = x[j];
        int  b = min((int)fmaf(v, scale, bias), 63);
        ntop += (v >= etop);
        atomicAdd(&shw[b], 1);
    }

    ntop = warp_sumi(ntop);
    __shared__ int swn[NTHR / 32];
    if (l == 0) swn[w] = ntop;
    __syncthreads();                         // all warp-hist atomics done

    // flush block totals to global
    if (threadIdx.x < NBINS) {
        int tsum = 0;
        #pragma unroll
        for (int c = 0; c < NTHR / 32; c++) tsum += sh[c][threadIdx.x];
        atomicAdd(&g_counts[threadIdx.x], tsum);
        __threadfence();
    }
    if (threadIdx.x == NBINS) {
        int tn = 0;
        #pragma unroll
        for (int c = 0; c < NTHR / 32; c++) tn += swn[c];
        if (tn) atomicAdd(&g_ntop, tn);
        __threadfence();
    }
    __syncthreads();                         // all per-thread fences complete
    if (threadIdx.x == 0)
        lastflag = (atomicAdd(&g_sem2, 1) == (int)gridDim.x - 1);
    __syncthreads();
    if (!lastflag) return;

    // ---- last block: write counts ----
    __threadfence();
    if (threadIdx.x < NBINS) {
        int c = g_counts[threadIdx.x];
        // Reference: elements >= edges[64] fall in no bin; then counts[-1] += 1.
        if (threadIdx.x == NBINS - 1) c += 1 - g_ntop;
        out[5 + 65 + threadIdx.x] = (float)c;
    }
    if (threadIdx.x == NBINS) g_sem2 = 0;    // re-arm for next replay
}

extern "C" void kernel_launch(void* const* d_in, const int* in_sizes, int n_in,
                              void* d_out, int out_size)
{
    const float* x = (const float*)d_in[0];
    int n = in_sizes[0];
    float* out = (float*)d_out;

    reduce_kernel<<<NBLK, NTHR>>>(x, n, out);
    hist_kernel  <<<NBLK, NTHR>>>(x, n, out);
}

// round 9
// speedup vs baseline: 1.2398x; 1.1943x over previous
#include <cuda_runtime.h>

#define NBLK  1216          // 152 SMs x 8 CTAs
#define NTHR  256
#define NBINS 64
#define NHIST 16            // 2 lane-parity copies x 8 warps

// Scratch (no allocations allowed).
__device__ float4 g_part[NBLK];     // per-block {min, max, sum, sumsq}
__device__ float  g_params[3];      // scale, bias, e_top(=edges[64])
__device__ int    g_counts[NBINS];
__device__ int    g_ntop;
__device__ int    g_sem1;           // zero-init; self-resetting tickets
__device__ int    g_sem2;

__device__ __forceinline__ float warp_min(float v) {
    #pragma unroll
    for (int o = 16; o; o >>= 1) v = fminf(v, __shfl_xor_sync(0xffffffffu, v, o));
    return v;
}
__device__ __forceinline__ float warp_max(float v) {
    #pragma unroll
    for (int o = 16; o; o >>= 1) v = fmaxf(v, __shfl_xor_sync(0xffffffffu, v, o));
    return v;
}
__device__ __forceinline__ float warp_sum(float v) {
    #pragma unroll
    for (int o = 16; o; o >>= 1) v += __shfl_xor_sync(0xffffffffu, v, o);
    return v;
}
__device__ __forceinline__ int warp_sumi(int v) {
    #pragma unroll
    for (int o = 16; o; o >>= 1) v += __shfl_xor_sync(0xffffffffu, v, o);
    return v;
}

// accumulate one float4 into one accumulator set
#define ACC(v, mn, mx, s, q)                                        \
    do {                                                            \
        mn = fminf(mn, fminf(fminf(v.x, v.y), fminf(v.z, v.w)));    \
        mx = fmaxf(mx, fmaxf(fmaxf(v.x, v.y), fmaxf(v.z, v.w)));    \
        s += (v.x + v.y) + (v.z + v.w);                             \
        q = fmaf(v.x, v.x, q); q = fmaf(v.y, v.y, q);               \
        q = fmaf(v.z, v.z, q); q = fmaf(v.w, v.w, q);               \
    } while (0)

// ---------------- Pass 1: min/max/sum/sumsq + fused finalization ----------------
// Iterates ASCENDING. In graph-replay steady state, the previous hist pass
// (descending) finished on the low-index region, so our first reads hit L2.
__global__ void __launch_bounds__(NTHR) reduce_kernel(const float* __restrict__ x,
                                                      int n, float* __restrict__ out)
{
    const float4* __restrict__ x4 = (const float4*)x;
    int n4     = n >> 2;
    int stride = gridDim.x * blockDim.x;
    int tid    = blockIdx.x * blockDim.x + threadIdx.x;

    float inf = __int_as_float(0x7f800000);
    float mn0 = inf, mn1 = inf, mx0 = -inf, mx1 = -inf;
    float s0 = 0.f, s1 = 0.f, q0 = 0.f, q1 = 0.f;

    // MLP=4: four independent 128-bit loads in flight per iteration
    int i = tid;
    for (; i < n4 - 3 * stride; i += 4 * stride) {
        float4 a = x4[i];
        float4 b = x4[i + stride];
        float4 c = x4[i + 2 * stride];
        float4 d = x4[i + 3 * stride];
        ACC(a, mn0, mx0, s0, q0);
        ACC(b, mn1, mx1, s1, q1);
        ACC(c, mn0, mx0, s0, q0);
        ACC(d, mn1, mx1, s1, q1);
    }
    for (; i < n4; i += stride) {
        float4 a = x4[i];
        ACC(a, mn0, mx0, s0, q0);
    }
    for (int j = (n4 << 2) + tid; j < n; j += stride) {   // scalar tail
        float v = x[j];
        mn0 = fminf(mn0, v);
        mx0 = fmaxf(mx0, v);
        s0 += v;
        q0 = fmaf(v, v, q0);
    }

    float lmn = warp_min(fminf(mn0, mn1));
    float lmx = warp_max(fmaxf(mx0, mx1));
    float ls  = warp_sum(s0 + s1);
    float lq  = warp_sum(q0 + q1);

    __shared__ float4 sred[NTHR / 32];
    __shared__ int    lastflag;
    int w = threadIdx.x >> 5, l = threadIdx.x & 31;
    if (l == 0) sred[w] = make_float4(lmn, lmx, ls, lq);
    __syncthreads();
    if (w == 0) {
        float4 v = (l < NTHR / 32) ? sred[l] : make_float4(inf, -inf, 0.f, 0.f);
        float a = warp_min(v.x);
        float b = warp_max(v.y);
        float c = warp_sum(v.z);
        float d = warp_sum(v.w);
        if (l == 0) {
            g_part[blockIdx.x] = make_float4(a, b, c, d);
            __threadfence();
            lastflag = (atomicAdd(&g_sem1, 1) == (int)gridDim.x - 1);
        }
    }
    __syncthreads();
    if (!lastflag) return;

    // ---- last block: final reduce + edges + scratch reset ----
    __threadfence();
    int t = threadIdx.x;
    if (t < NBINS)      g_counts[t] = 0;
    if (t == NBINS)     g_ntop = 0;
    if (t == NBINS + 1) g_sem1 = 0;      // re-arm for next graph replay

    float mnA = inf, mxA = -inf, s = 0.f, q = 0.f;
    for (int k = t; k < NBLK; k += NTHR) {
        float4 v = g_part[k];
        mnA = fminf(mnA, v.x);
        mxA = fmaxf(mxA, v.y);
        s += v.z;
        q += v.w;
    }
    mnA = warp_min(mnA); mxA = warp_max(mxA); s = warp_sum(s); q = warp_sum(q);

    __shared__ float4 sred2[NTHR / 32];
    __shared__ float  fin[4];
    if (l == 0) sred2[w] = make_float4(mnA, mxA, s, q);
    __syncthreads();
    if (w == 0) {
        float4 v = (l < NTHR / 32) ? sred2[l] : make_float4(inf, -inf, 0.f, 0.f);
        float a = warp_min(v.x);
        float b = warp_max(v.y);
        float c = warp_sum(v.z);
        float d = warp_sum(v.w);
        if (l == 0) { fin[0] = a; fin[1] = b; fin[2] = c; fin[3] = d; }
    }
    __syncthreads();

    float mn = fin[0], mx = fin[1];
    float r  = __fadd_rn(mx, -mn);          // fl(mx - mn), matches reference
    if (t == 0) {
        out[0] = mn;
        out[1] = mx;
        out[2] = (float)n;
        out[3] = fin[2];
        out[4] = fin[3];
        float scale = __fdiv_rn(64.0f, r);
        g_params[0] = scale;
        g_params[1] = -mn * scale;
        g_params[2] = __fadd_rn(mn, r);     // edges[64] (overflow boundary)
    }
    if (t <= NBINS) {
        // edges[j] = fl(mn + fl(r * fl(j/64))) — j/64 exact dyadic, unfused ops
        float frac = (float)t * 0.015625f;
        out[5 + t] = __fadd_rn(mn, __fmul_rn(r, frac));
    }
}

// bin + count one float4 into a sub-histogram
#define BIN4(v, shw, ntop, scale, bias, etop)                      \
    do {                                                           \
        int b0 = min((int)fmaf(v.x, scale, bias), 63);             \
        int b1 = min((int)fmaf(v.y, scale, bias), 63);             \
        int b2 = min((int)fmaf(v.z, scale, bias), 63);             \
        int b3 = min((int)fmaf(v.w, scale, bias), 63);             \
        ntop += (v.x >= etop) + (v.y >= etop) +                    \
                (v.z >= etop) + (v.w >= etop);                     \
        atomicAdd(&shw[b0], 1);                                    \
        atomicAdd(&shw[b1], 1);                                    \
        atomicAdd(&shw[b2], 1);                                    \
        atomicAdd(&shw[b3], 1);                                    \
    } while (0)

// ---------------- Pass 2: histogram + fused finalization ----------------
// Iterates DESCENDING over the same index set, so its first reads hit the
// ~126MB the reduce pass most recently pulled into L2.
__global__ void __launch_bounds__(NTHR) hist_kernel(const float* __restrict__ x,
                                                    int n, float* __restrict__ out)
{
    __shared__ int sh[NHIST][NBINS];         // 2 lane-parity copies per warp
    __shared__ int lastflag;
    int w = threadIdx.x >> 5, l = threadIdx.x & 31;
    #pragma unroll
    for (int k = 0; k < NHIST * NBINS / NTHR; k++)
        ((int*)sh)[threadIdx.x + k * NTHR] = 0;
    __syncthreads();
    int* shw = sh[w * 2 + (l & 1)];          // halve intra-warp conflict degree

    float scale = g_params[0];
    float bias  = g_params[1];
    float etop  = g_params[2];

    const float4* __restrict__ x4 = (const float4*)x;
    int n4      = n >> 2;
    int stride  = gridDim.x * blockDim.x;
    int stride4 = 4 * stride;
    int tid     = blockIdx.x * blockDim.x + threadIdx.x;
    int ntop    = 0;

    // number of full 4-batched chunks (same index set as an ascending walk)
    int lim = n4 - 3 * stride;
    int C   = (lim > tid) ? (lim - tid + stride4 - 1) / stride4 : 0;

    // scalar tail first (highest addresses)
    for (int j = (n4 << 2) + tid; j < n; j += stride) {
        float v = x[j];
        int  b = min((int)fmaf(v, scale, bias), 63);
        ntop += (v >= etop);
        atomicAdd(&shw[b], 1);
    }
    // remainder float4s (next-highest addresses)
    for (int i = tid + C * stride4; i < n4; i += stride) {
        float4 a = x4[i];
        BIN4(a, shw, ntop, scale, bias, etop);
    }
    // main chunks, descending
    for (int c = C - 1; c >= 0; --c) {
        int i = tid + c * stride4;
        float4 a = x4[i];
        float4 b = x4[i + stride];
        float4 d = x4[i + 2 * stride];
        float4 e = x4[i + 3 * stride];
        BIN4(e, shw, ntop, scale, bias, etop);
        BIN4(d, shw, ntop, scale, bias, etop);
        BIN4(b, shw, ntop, scale, bias, etop);
        BIN4(a, shw, ntop, scale, bias, etop);
    }

    ntop = warp_sumi(ntop);
    __shared__ int swn[NTHR / 32];
    if (l == 0) swn[w] = ntop;
    __syncthreads();                         // all sub-hist atomics done

    // flush block totals to global
    if (threadIdx.x < NBINS) {
        int tsum = 0;
        #pragma unroll
        for (int c = 0; c < NHIST; c++) tsum += sh[c][threadIdx.x];
        atomicAdd(&g_counts[threadIdx.x], tsum);
        __threadfence();
    }
    if (threadIdx.x == NBINS) {
        int tn = 0;
        #pragma unroll
        for (int c = 0; c < NTHR / 32; c++) tn += swn[c];
        if (tn) atomicAdd(&g_ntop, tn);
        __threadfence();
    }
    __syncthreads();                         // all per-thread fences complete
    if (threadIdx.x == 0)
        lastflag = (atomicAdd(&g_sem2, 1) == (int)gridDim.x - 1);
    __syncthreads();
    if (!lastflag) return;

    // ---- last block: write counts ----
    __threadfence();
    if (threadIdx.x < NBINS) {
        int c = g_counts[threadIdx.x];
        // Reference: elements >= edges[64] fall in no bin; then counts[-1] += 1.
        if (threadIdx.x == NBINS - 1) c += 1 - g_ntop;
        out[5 + 65 + threadIdx.x] = (float)c;
    }
    if (threadIdx.x == NBINS) g_sem2 = 0;    // re-arm for next replay
}

extern "C" void kernel_launch(void* const* d_in, const int* in_sizes, int n_in,
                              void* d_out, int out_size)
{
    const float* x = (const float*)d_in[0];
    int n = in_sizes[0];
    float* out = (float*)d_out;

    reduce_kernel<<<NBLK, NTHR>>>(x, n, out);
    hist_kernel  <<<NBLK, NTHR>>>(x, n, out);
}